// round 8
// baseline (speedup 1.0000x reference)
#include <cuda_runtime.h>

// GCBFSafetyLayer — FINAL (terminal at the graph-replay floor).
//
// Math: the reference QP projection passes A = L_g_h = jnp.zeros(...) into
// the per-constraint solver; every update is gated by (nrm > 1e-6) with
// nrm = sum(a_j^2) = 0, so the gate is always false and the scan/fori_loop
// return u0 unchanged. safe_action == raw_action bit-exactly (rel_err = 0.0
// on all 7 benched rounds). Work reduces to one 32 KB D2D move of
// d_in[3] -> d_out.
//
// Measured sweep (total us): 1x256: 6.62 | 32x64: 6.88 | 8x256: 4.61 |
// 16x128: 4.58, 4.61 | driver memcpy node: 4.58. Best configs tie within
// one 32ns timer tick while kernel-internal time wanders 3.55-4.06us on
// identical binaries -> total is pinned by graph-replay + single-node
// dispatch overhead. Nothing in the kernel remains on the critical path.

__global__ void __launch_bounds__(128, 1)
copy_exact_kernel(const float4* __restrict__ src, float4* __restrict__ dst) {
    // blockDim is compile-time known (128): saves an S2R in SASS.
    int i = blockIdx.x * 128 + threadIdx.x;
    dst[i] = src[i];
}

// Generic fallback for unexpected sizes.
__global__ void copy_generic_kernel(const float* __restrict__ src,
                                    float* __restrict__ dst, int n) {
    int i = blockIdx.x * blockDim.x + threadIdx.x;
    if (i < n) dst[i] = src[i];
}

extern "C" void kernel_launch(void* const* d_in, const int* in_sizes, int n_in,
                              void* d_out, int out_size) {
    const float* raw_action = (const float*)d_in[3];
    float* out = (float*)d_out;

    if ((out_size & 511) == 0) {
        // Multiple of 512 floats: grid = out_size/512 blocks of 128 threads,
        // one float4 per thread. For 8192 floats -> grid=16 (measured best).
        int blocks = out_size / 512;
        copy_exact_kernel<<<blocks, 128>>>((const float4*)raw_action,
                                           (float4*)out);
    } else {
        int threads = 256;
        int blocks = (out_size + threads - 1) / threads;
        copy_generic_kernel<<<blocks, threads>>>(raw_action, out, out_size);
    }
}

// round 9
// speedup vs baseline: 1.2119x; 1.2119x over previous
#include <cuda_runtime.h>

// GCBFSafetyLayer — FINAL (terminal at the graph-replay floor).
//
// Math: the reference QP projection passes A = L_g_h = jnp.zeros(...) into
// the per-constraint solver; every update is gated by (nrm > 1e-6) with
// nrm = sum(a_j^2) = 0, so the gate is always false and scan/fori_loop
// return u0 unchanged. safe_action == raw_action bit-exactly (rel_err = 0.0
// on all 8 benched rounds). Work reduces to one 32 KB D2D move of
// d_in[3] -> d_out.
//
// Evidence of floor (9 runs): best totals 4.576/4.58/4.608us are ties among
// 16x128 kernel node, 8x256 kernel node, and driver memcpy node. Kernel-
// internal time for identical binaries wanders 3.55-4.06us; run-level total
// jitter spans 4.58-5.86us (R8: best-ever kernel time 3.68us inside a
// 5.86us total). The duration is graph-replay + single-node dispatch
// overhead; the copy (~8ns of HBM time at 8TB/s) is invisible. Swept and
// exhausted: node mechanism, grid {1,8,16,32}, block {64,128,256},
// branchy/branchless, unroll, constant blockDim. grid=1 and 32x64 are the
// only genuine regressions (single-SM L1tex queue / latency-exposed 2-warp
// blocks).

__global__ void __launch_bounds__(128, 1)
copy_exact_kernel(const float4* __restrict__ src, float4* __restrict__ dst) {
    // blockDim compile-time constant (128): body is IMAD + LDG.128 +
    // STG.128 + EXIT.
    int i = blockIdx.x * 128 + threadIdx.x;
    dst[i] = src[i];
}

// Generic fallback for unexpected sizes.
__global__ void copy_generic_kernel(const float* __restrict__ src,
                                    float* __restrict__ dst, int n) {
    int i = blockIdx.x * blockDim.x + threadIdx.x;
    if (i < n) dst[i] = src[i];
}

extern "C" void kernel_launch(void* const* d_in, const int* in_sizes, int n_in,
                              void* d_out, int out_size) {
    const float* raw_action = (const float*)d_in[3];
    float* out = (float*)d_out;

    if ((out_size & 511) == 0) {
        // Multiple of 512 floats: grid = out_size/512 blocks of 128 threads,
        // one float4 per thread. For 8192 floats -> grid=16 (measured best).
        int blocks = out_size / 512;
        copy_exact_kernel<<<blocks, 128>>>((const float4*)raw_action,
                                           (float4*)out);
    } else {
        int threads = 256;
        int blocks = (out_size + threads - 1) / threads;
        copy_generic_kernel<<<blocks, threads>>>(raw_action, out, out_size);
    }
}

// round 10
// speedup vs baseline: 1.2708x; 1.0486x over previous
#include <cuda_runtime.h>

// GCBFSafetyLayer — FINAL (terminal at the graph-replay floor).
//
// Math: the reference QP projection passes A = L_g_h = jnp.zeros(...) into
// the per-constraint solver; every update is gated by (nrm > 1e-6) with
// nrm = sum(a_j^2) = 0, so the gate is always false and scan/fori_loop
// return u0 unchanged. safe_action == raw_action bit-exactly (rel_err = 0.0
// on all 9 benched rounds). Work reduces to one 32 KB D2D move of
// d_in[3] -> d_out (~8ns of HBM time at 8TB/s).
//
// Evidence of floor (10 runs): champion config (16x128 kernel node) samples
// 4.576/4.608/5.856/4.832us on an identical binary; driver memcpy node ties
// at 4.58us; 8x256 ties at 4.61us. Kernel-internal time wanders
// 3.55-4.06us with issue<1%, DRAM 0.1%. The total is graph-replay +
// single-node dispatch overhead. Swept and exhausted: node mechanism,
// grid {1,8,16,32}, block {64,128,256}, branchy/branchless, unroll,
// constant blockDim. Genuine regressions only at grid=1 (single-SM L1tex
// queue serialization) and 32x64 (latency-exposed 2-warp blocks).

__global__ void __launch_bounds__(128, 1)
copy_exact_kernel(const float4* __restrict__ src, float4* __restrict__ dst) {
    // blockDim compile-time constant (128): body is IMAD + LDG.128 +
    // STG.128 + EXIT.
    int i = blockIdx.x * 128 + threadIdx.x;
    dst[i] = src[i];
}

// Generic fallback for unexpected sizes.
__global__ void copy_generic_kernel(const float* __restrict__ src,
                                    float* __restrict__ dst, int n) {
    int i = blockIdx.x * blockDim.x + threadIdx.x;
    if (i < n) dst[i] = src[i];
}

extern "C" void kernel_launch(void* const* d_in, const int* in_sizes, int n_in,
                              void* d_out, int out_size) {
    const float* raw_action = (const float*)d_in[3];
    float* out = (float*)d_out;

    if ((out_size & 511) == 0) {
        // Multiple of 512 floats: grid = out_size/512 blocks of 128 threads,
        // one float4 per thread. For 8192 floats -> grid=16 (measured best).
        int blocks = out_size / 512;
        copy_exact_kernel<<<blocks, 128>>>((const float4*)raw_action,
                                           (float4*)out);
    } else {
        int threads = 256;
        int blocks = (out_size + threads - 1) / threads;
        copy_generic_kernel<<<blocks, threads>>>(raw_action, out, out_size);
    }
}